// round 11
// baseline (speedup 1.0000x reference)
#include <cuda_runtime.h>
#include <math.h>

#define Bn   65536
#define Tn   5
#define BT   (Bn*Tn)
#define EPSf 1e-12f

typedef unsigned long long u64;

__device__ float g_x[BT * 64];          // zero-init; invalid (t>=au) slots never written
__device__ float g_ys[2][BT * 64];
__device__ int   g_cnt[5];
__device__ int   g_cursor[5];
__device__ int   g_pbase[5];
__device__ int   g_vbase[6];
__device__ int   g_perm[Bn];

extern __shared__ float smem[];

__device__ __forceinline__ u64 splat2(float x) {
    u64 r; asm("mov.b64 %0, {%1, %1};" : "=l"(r) : "f"(x)); return r;
}
__device__ __forceinline__ void ffma2(u64& d, u64 a, u64 b) {
    asm("fma.rn.f32x2 %0, %1, %2, %0;" : "+l"(d) : "l"(a), "l"(b));
}
__device__ __forceinline__ void lds_v2u64(u64& a, u64& b, unsigned addr) {
    asm volatile("ld.shared.v2.u64 {%0, %1}, [%2];" : "=l"(a), "=l"(b) : "r"(addr));
}
__device__ __forceinline__ float2 unpack2(u64 v) {
    float2 f; asm("mov.b64 {%0, %1}, %2;" : "=f"(f.x), "=f"(f.y) : "l"(v)); return f;
}
__device__ __forceinline__ float sig_f(float x) { return __fdividef(1.f, 1.f + __expf(-x)); }
__device__ __forceinline__ float tanh_f(float x) { return __fdividef(2.f, 1.f + __expf(-2.f * x)) - 1.f; }

#define CP16(dst, src) asm volatile("cp.async.ca.shared.global [%0], [%1], 16;" :: "r"(dst), "l"(src))
#define CP_COMMIT()    asm volatile("cp.async.commit_group;")

// ============================ au counting sort ======================================
__global__ void zero_cnt_kernel() {
    if (threadIdx.x < 5) g_cnt[threadIdx.x] = 0;
}
__global__ __launch_bounds__(512)
void hist_kernel(const int* __restrict__ au) {
    __shared__ int h[5];
    int tid = threadIdx.x;
    if (tid < 5) h[tid] = 0;
    __syncthreads();
    atomicAdd(&h[5 - au[blockIdx.x * 512 + tid]], 1);
    __syncthreads();
    if (tid < 5) atomicAdd(&g_cnt[tid], h[tid]);
}
__global__ void prefix_kernel() {
    if (threadIdx.x == 0) {
        int s = 0, vs = 0;
        #pragma unroll
        for (int i = 0; i < 5; i++) {
            int c = g_cnt[i];
            g_cursor[i] = s;
            g_pbase[i]  = s;
            g_vbase[i]  = vs;
            s  += c;
            vs += c * (5 - i);
        }
        g_vbase[5] = vs;
    }
}
__global__ __launch_bounds__(512)
void scatter_kernel(const int* __restrict__ au) {
    int i = blockIdx.x * 512 + threadIdx.x;
    int lane = threadIdx.x & 31;
    int bkt = 5 - au[i];
    unsigned m = __match_any_sync(0xffffffffu, bkt);
    int leader = __ffs(m) - 1;
    int rank = __popc(m & ((1u << lane) - 1u));
    int base = 0;
    if (lane == leader) base = atomicAdd(&g_cursor[bkt], __popc(m));
    base = __shfl_sync(0xffffffffu, base, leader);
    g_perm[base + rank] = i;
}

// ============================ Kernel 1: fused MLP (valid rows; 4x8 tile) ============
// 64 valid rows/CTA, 128 threads, 2 CTA/SM. Thread tile = 4 rows x 8 cols:
// each A-splat feeds 4 FFMA2 (was 2) -> ALU halved, issue 84% of FMA budget.
__global__ __launch_bounds__(128)
void mlp_kernel(const float* __restrict__ ud, const float* __restrict__ act,
                const float* __restrict__ ln0g, const float* __restrict__ ln0b,
                const float* __restrict__ W1, const float* __restrict__ b1,
                const float* __restrict__ ln1g, const float* __restrict__ ln1b,
                const float* __restrict__ W2, const float* __restrict__ b2,
                const float* __restrict__ ln2g, const float* __restrict__ ln2b)
{
    const int vtot = g_vbase[5];
    if (blockIdx.x * 64 >= vtot) return;

    float* sW  = smem;                 // 8192 floats (W1, then W2)
    float* sX  = sW + 128 * 64;        // 64 * 132
    float* sX2 = sX + 64 * 132;        // 64 * 100
    float* sP  = sX2 + 64 * 100;       // 640
    int*   sRowIdx = (int*)(sP + 640); // 64

    const unsigned sW_a = (unsigned)__cvta_generic_to_shared(sW);
    const int tid = threadIdx.x;

    // W1: 2048 float4, 128 threads -> 16 iters
    #pragma unroll
    for (int j = 0; j < 16; j++) {
        int f = tid + j * 128;
        reinterpret_cast<float4*>(sW)[f] = reinterpret_cast<const float4*>(W1)[f];
    }
    sP[tid] = ln0g[tid]; sP[128 + tid] = ln0b[tid];
    if (tid < 64) {
        sP[256 + tid] = b1[tid];  sP[320 + tid] = ln1g[tid]; sP[384 + tid] = ln1b[tid];
        sP[448 + tid] = b2[tid];  sP[512 + tid] = ln2g[tid]; sP[576 + tid] = ln2b[tid];
    }

    // ---- map 64 flat valid indices -> global rows ----
    if (tid < 64) {
        int v = blockIdx.x * 64 + tid;
        int row = -1;
        if (v < vtot) {
            int k = 0;
            #pragma unroll
            for (int j = 1; j < 5; j++) if (v >= g_vbase[j]) k = j;
            int L = 5 - k;
            int idx = v - g_vbase[k];
            int q = idx / L;
            int t = idx - q * L;
            int b = g_perm[g_pbase[k] + q];
            row = b * 5 + t;
        }
        sRowIdx[tid] = row;
    }
    __syncthreads();

    // ud tile: 2048 float4 -> 16 iters
    #pragma unroll
    for (int j = 0; j < 16; j++) {
        int f = tid + j * 128;
        int row = f >> 5, c4 = f & 31;
        int gr = sRowIdx[row];
        float4 v = make_float4(0.f, 0.f, 0.f, 0.f);
        if (gr >= 0) v = reinterpret_cast<const float4*>(ud + (size_t)gr * 128)[c4];
        *reinterpret_cast<float4*>(&sX[row * 132 + c4 * 4]) = v;
    }
    // action tile: 512 float4 -> 4 iters
    #pragma unroll
    for (int j = 0; j < 4; j++) {
        int f = tid + j * 128;
        int row = f >> 3, c4 = f & 7;
        int gr = sRowIdx[row];
        float4 v = make_float4(0.f, 0.f, 0.f, 0.f);
        if (gr >= 0) v = reinterpret_cast<const float4*>(act + (size_t)gr * 32)[c4];
        *reinterpret_cast<float4*>(&sX2[row * 100 + 64 + c4 * 4]) = v;
    }
    __syncthreads();

    const int w = tid >> 5, lane = tid & 31;

    // LN0 over 128 features (warp per row, 16 rows/warp)
    for (int rr = 0; rr < 16; rr++) {
        int row = w * 16 + rr;
        float v0 = sX[row * 132 + lane];
        float v1 = sX[row * 132 + lane + 32];
        float v2 = sX[row * 132 + lane + 64];
        float v3 = sX[row * 132 + lane + 96];
        float s = v0 + v1 + v2 + v3;
        float q = v0 * v0 + v1 * v1 + v2 * v2 + v3 * v3;
        #pragma unroll
        for (int o = 16; o; o >>= 1) { s += __shfl_xor_sync(~0u, s, o); q += __shfl_xor_sync(~0u, q, o); }
        float m = s * (1.f / 128.f);
        float var = q * (1.f / 128.f) - m * m;
        float rs = rsqrtf(var + EPSf);
        sX[row * 132 + lane]      = (v0 - m) * rs * sP[lane]      + sP[128 + lane];
        sX[row * 132 + lane + 32] = (v1 - m) * rs * sP[lane + 32] + sP[128 + lane + 32];
        sX[row * 132 + lane + 64] = (v2 - m) * rs * sP[lane + 64] + sP[128 + lane + 64];
        sX[row * 132 + lane + 96] = (v3 - m) * rs * sP[lane + 96] + sP[128 + lane + 96];
    }
    __syncthreads();

    const int ty = tid >> 3, tx = tid & 7;      // 16 row-groups x 8 col-groups
    const int ry = ty * 4, cx = tx * 8;

    // GEMM1: (64x128)@(128x64), thread tile 4 rows x 8 cols
    u64 acc[4][4];
    #pragma unroll
    for (int i = 0; i < 4; i++)
        #pragma unroll
        for (int e = 0; e < 4; e++) acc[i][e] = 0ull;

    for (int k = 0; k < 128; k += 4) {
        float4 a4[4];
        #pragma unroll
        for (int i = 0; i < 4; i++)
            a4[i] = *reinterpret_cast<const float4*>(&sX[(ry + i) * 132 + k]);
        #pragma unroll
        for (int kk = 0; kk < 4; kk++) {
            u64 w0, w1, w2, w3;
            lds_v2u64(w0, w1, sW_a + (unsigned)((k + kk) * 64 + cx) * 4u);
            lds_v2u64(w2, w3, sW_a + (unsigned)((k + kk) * 64 + cx + 4) * 4u);
            #pragma unroll
            for (int i = 0; i < 4; i++) {
                u64 s = splat2((&a4[i].x)[kk]);
                ffma2(acc[i][0], s, w0);
                ffma2(acc[i][1], s, w1);
                ffma2(acc[i][2], s, w2);
                ffma2(acc[i][3], s, w3);
            }
        }
    }
    __syncthreads();   // sW(W1)+sX reads done

    // load W2 (1536 float4 -> 12 iters) while epilogue runs
    #pragma unroll
    for (int j = 0; j < 12; j++) {
        int f = tid + j * 128;
        reinterpret_cast<float4*>(sW)[f] = reinterpret_cast<const float4*>(W2)[f];
    }

    // ---- in-register LN1 + relu -> sX2 cols [0,64) (8-lane shfl reduction) ----
    {
        #pragma unroll
        for (int i = 0; i < 4; i++) {
            float v[8];
            #pragma unroll
            for (int e = 0; e < 4; e++) {
                float2 p = unpack2(acc[i][e]);
                v[e * 2]     = p.x + sP[256 + cx + e * 2];
                v[e * 2 + 1] = p.y + sP[256 + cx + e * 2 + 1];
            }
            float s = 0.f, q = 0.f;
            #pragma unroll
            for (int e = 0; e < 8; e++) { s += v[e]; q += v[e] * v[e]; }
            #pragma unroll
            for (int o = 1; o < 8; o <<= 1) { s += __shfl_xor_sync(~0u, s, o); q += __shfl_xor_sync(~0u, q, o); }
            float m = s * (1.f / 64.f);
            float var = q * (1.f / 64.f) - m * m;
            float rs = rsqrtf(var + EPSf);
            float4 oA, oB;
            oA.x = fmaxf((v[0] - m) * rs * sP[320 + cx + 0] + sP[384 + cx + 0], 0.f);
            oA.y = fmaxf((v[1] - m) * rs * sP[320 + cx + 1] + sP[384 + cx + 1], 0.f);
            oA.z = fmaxf((v[2] - m) * rs * sP[320 + cx + 2] + sP[384 + cx + 2], 0.f);
            oA.w = fmaxf((v[3] - m) * rs * sP[320 + cx + 3] + sP[384 + cx + 3], 0.f);
            oB.x = fmaxf((v[4] - m) * rs * sP[320 + cx + 4] + sP[384 + cx + 4], 0.f);
            oB.y = fmaxf((v[5] - m) * rs * sP[320 + cx + 5] + sP[384 + cx + 5], 0.f);
            oB.z = fmaxf((v[6] - m) * rs * sP[320 + cx + 6] + sP[384 + cx + 6], 0.f);
            oB.w = fmaxf((v[7] - m) * rs * sP[320 + cx + 7] + sP[384 + cx + 7], 0.f);
            *reinterpret_cast<float4*>(&sX2[(ry + i) * 100 + cx])     = oA;
            *reinterpret_cast<float4*>(&sX2[(ry + i) * 100 + cx + 4]) = oB;
        }
    }
    __syncthreads();   // W2 + sX2 ready

    // GEMM2: (64x96)@(96x64)
    u64 acc2[4][4];
    #pragma unroll
    for (int i = 0; i < 4; i++)
        #pragma unroll
        for (int e = 0; e < 4; e++) acc2[i][e] = 0ull;

    for (int k = 0; k < 96; k += 4) {
        float4 a4[4];
        #pragma unroll
        for (int i = 0; i < 4; i++)
            a4[i] = *reinterpret_cast<const float4*>(&sX2[(ry + i) * 100 + k]);
        #pragma unroll
        for (int kk = 0; kk < 4; kk++) {
            u64 w0, w1, w2, w3;
            lds_v2u64(w0, w1, sW_a + (unsigned)((k + kk) * 64 + cx) * 4u);
            lds_v2u64(w2, w3, sW_a + (unsigned)((k + kk) * 64 + cx + 4) * 4u);
            #pragma unroll
            for (int i = 0; i < 4; i++) {
                u64 s = splat2((&a4[i].x)[kk]);
                ffma2(acc2[i][0], s, w0);
                ffma2(acc2[i][1], s, w1);
                ffma2(acc2[i][2], s, w2);
                ffma2(acc2[i][3], s, w3);
            }
        }
    }

    // ---- in-register LN2 + relu -> g_x (guarded scatter store) ----
    {
        #pragma unroll
        for (int i = 0; i < 4; i++) {
            float v[8];
            #pragma unroll
            for (int e = 0; e < 4; e++) {
                float2 p = unpack2(acc2[i][e]);
                v[e * 2]     = p.x + sP[448 + cx + e * 2];
                v[e * 2 + 1] = p.y + sP[448 + cx + e * 2 + 1];
            }
            float s = 0.f, q = 0.f;
            #pragma unroll
            for (int e = 0; e < 8; e++) { s += v[e]; q += v[e] * v[e]; }
            #pragma unroll
            for (int o = 1; o < 8; o <<= 1) { s += __shfl_xor_sync(~0u, s, o); q += __shfl_xor_sync(~0u, q, o); }
            float m = s * (1.f / 64.f);
            float var = q * (1.f / 64.f) - m * m;
            float rs = rsqrtf(var + EPSf);
            int gr = sRowIdx[ry + i];
            if (gr >= 0) {
                float4 oA, oB;
                oA.x = fmaxf((v[0] - m) * rs * sP[512 + cx + 0] + sP[576 + cx + 0], 0.f);
                oA.y = fmaxf((v[1] - m) * rs * sP[512 + cx + 1] + sP[576 + cx + 1], 0.f);
                oA.z = fmaxf((v[2] - m) * rs * sP[512 + cx + 2] + sP[576 + cx + 2], 0.f);
                oA.w = fmaxf((v[3] - m) * rs * sP[512 + cx + 3] + sP[576 + cx + 3], 0.f);
                oB.x = fmaxf((v[4] - m) * rs * sP[512 + cx + 4] + sP[576 + cx + 4], 0.f);
                oB.y = fmaxf((v[5] - m) * rs * sP[512 + cx + 5] + sP[576 + cx + 5], 0.f);
                oB.z = fmaxf((v[6] - m) * rs * sP[512 + cx + 6] + sP[576 + cx + 6], 0.f);
                oB.w = fmaxf((v[7] - m) * rs * sP[512 + cx + 7] + sP[576 + cx + 7], 0.f);
                *reinterpret_cast<float4*>(&g_x[(size_t)gr * 64 + cx])     = oA;
                *reinterpret_cast<float4*>(&g_x[(size_t)gr * 64 + cx + 4]) = oB;
            }
        }
    }
}

// ===================== Kernel 2: persistent LSTM (R10, proven) ======================
#define LSTM_K(wk, A_a, astr, ak) do {                                                   \
    float4 wij = *reinterpret_cast<const float4*>(sKp + (wk) * 256 + hp * 8);            \
    float4 wfo = *reinterpret_cast<const float4*>(sKp + (wk) * 256 + hp * 8 + 4);        \
    u64 a01, a23, a45, a67;                                                              \
    lds_v2u64(a01, a23, (A_a) + (unsigned)((ak) * (astr) + r0) * 4u);                    \
    lds_v2u64(a45, a67, (A_a) + (unsigned)((ak) * (astr) + r0 + 4) * 4u);                \
    u64 s_;                                                                              \
    s_ = splat2(wij.x); ffma2(acc[0][0][0],s_,a01); ffma2(acc[0][0][1],s_,a23);          \
                        ffma2(acc[0][0][2],s_,a45); ffma2(acc[0][0][3],s_,a67);          \
    s_ = splat2(wij.y); ffma2(acc[0][1][0],s_,a01); ffma2(acc[0][1][1],s_,a23);          \
                        ffma2(acc[0][1][2],s_,a45); ffma2(acc[0][1][3],s_,a67);          \
    s_ = splat2(wij.z); ffma2(acc[1][0][0],s_,a01); ffma2(acc[1][0][1],s_,a23);          \
                        ffma2(acc[1][0][2],s_,a45); ffma2(acc[1][0][3],s_,a67);          \
    s_ = splat2(wij.w); ffma2(acc[1][1][0],s_,a01); ffma2(acc[1][1][1],s_,a23);          \
                        ffma2(acc[1][1][2],s_,a45); ffma2(acc[1][1][3],s_,a67);          \
    s_ = splat2(wfo.x); ffma2(acc[2][0][0],s_,a01); ffma2(acc[2][0][1],s_,a23);          \
                        ffma2(acc[2][0][2],s_,a45); ffma2(acc[2][0][3],s_,a67);          \
    s_ = splat2(wfo.y); ffma2(acc[2][1][0],s_,a01); ffma2(acc[2][1][1],s_,a23);          \
                        ffma2(acc[2][1][2],s_,a45); ffma2(acc[2][1][3],s_,a67);          \
    s_ = splat2(wfo.z); ffma2(acc[3][0][0],s_,a01); ffma2(acc[3][0][1],s_,a23);          \
                        ffma2(acc[3][0][2],s_,a45); ffma2(acc[3][0][3],s_,a67);          \
    s_ = splat2(wfo.w); ffma2(acc[3][1][0],s_,a01); ffma2(acc[3][1][1],s_,a23);          \
                        ffma2(acc[3][1][2],s_,a45); ffma2(acc[3][1][3],s_,a67);          \
} while (0)

__global__ __launch_bounds__(512, 1)
void lstm_persistent_kernel(const float* __restrict__ fw_k, const float* __restrict__ fw_b,
                            const float* __restrict__ bw_k, const float* __restrict__ bw_b,
                            const int* __restrict__ au)
{
    float* sKp   = smem;                   // 32768: permuted weights
    float* stage = smem + 32768;           // 8192: raw x tile [128][64]
    float* xT    = smem + 40960;           // 8192: [64 k][128 rows]
    float* sHT   = smem + 49152;           // 8448: [64 hc][132]
    int*   sAu   = (int*)(smem + 57600);   // 128
    int*   sPb   = sAu + 128;              // 128

    const unsigned xT_a  = (unsigned)__cvta_generic_to_shared(xT);
    const unsigned sHT_a = (unsigned)__cvta_generic_to_shared(sHT);

    const int dir = blockIdx.y;
    const float* K    = dir ? bw_k : fw_k;
    const float* bias = dir ? bw_b : fw_b;
    float* gy = g_ys[dir];

    const int b0   = blockIdx.x * 128;
    const int tid  = threadIdx.x;
    const int lane = tid & 31, w = tid >> 5;
    const int hsub = lane & 7, rsub = lane >> 3;
    const int wcol = w & 3,  wrow = w >> 2;
    const int hp   = wcol * 8 + hsub;
    const int hx   = hp * 2;
    const int r0   = (wrow * 4 + rsub) * 8;

    const int mx = au[g_perm[b0]];

    {
        int row = tid >> 2, seg = tid & 3;
        int pb = g_perm[b0 + row];
        int a = au[pb];
        int ts = dir ? (a - 1) : 0;
        const float* src = g_x + ((size_t)pb * 5 + ts) * 64 + seg * 16;
        unsigned dst = (unsigned)__cvta_generic_to_shared(stage + row * 64 + seg * 16);
        #pragma unroll
        for (int q = 0; q < 4; q++) CP16(dst + q * 16, src + q * 4);
        CP_COMMIT();
        if (seg == 0) { sAu[row] = a; sPb[row] = pb; }
    }

    #pragma unroll
    for (int it = 0; it < 16; it++) {
        int f = tid + it * 512;
        int kk = f >> 6, c4 = f & 63;
        float4 v = reinterpret_cast<const float4*>(K + (size_t)kk * 256)[c4];
        int g   = c4 >> 4;
        int hp0 = (c4 & 15) * 2;
        *reinterpret_cast<float2*>(&sKp[kk * 256 + hp0 * 8 + g * 2])       = make_float2(v.x, v.y);
        *reinterpret_cast<float2*>(&sKp[kk * 256 + (hp0 + 1) * 8 + g * 2]) = make_float2(v.z, v.w);
    }

    float2 bg[4];
    #pragma unroll
    for (int g = 0; g < 4; g++)
        bg[g] = *reinterpret_cast<const float2*>(bias + g * 64 + hx);

    float2 cc[8];
    #pragma unroll
    for (int i = 0; i < 8; i++) cc[i] = make_float2(0.f, 0.f);

    for (int t = 0; t < mx; t++) {
        asm volatile("cp.async.wait_group 0;" ::: "memory");
        __syncthreads();

        {
            int row = tid >> 2, kc = (tid & 3) * 16;
            #pragma unroll
            for (int q = 0; q < 4; q++) {
                float4 v = *reinterpret_cast<const float4*>(&stage[row * 64 + kc + q * 4]);
                xT[(kc + q * 4 + 0) * 128 + row] = v.x;
                xT[(kc + q * 4 + 1) * 128 + row] = v.y;
                xT[(kc + q * 4 + 2) * 128 + row] = v.z;
                xT[(kc + q * 4 + 3) * 128 + row] = v.w;
            }
        }
        __syncthreads();

        if (t + 1 < mx) {
            int row = tid >> 2, seg = tid & 3;
            int pb = sPb[row];
            int a = sAu[row];
            int tt = t + 1;
            int ts = dir ? ((tt < a) ? (a - 1 - tt) : tt) : tt;
            const float* src = g_x + ((size_t)pb * 5 + ts) * 64 + seg * 16;
            unsigned dst = (unsigned)__cvta_generic_to_shared(stage + row * 64 + seg * 16);
            #pragma unroll
            for (int q = 0; q < 4; q++) CP16(dst + q * 16, src + q * 4);
            CP_COMMIT();
        } else {
            CP_COMMIT();
        }

        u64 acc[4][2][4];
        #pragma unroll
        for (int g = 0; g < 4; g++)
            #pragma unroll
            for (int e = 0; e < 2; e++)
                #pragma unroll
                for (int rp = 0; rp < 4; rp++) acc[g][e][rp] = 0ull;

        #pragma unroll 2
        for (int k = 0; k < 64; k++) LSTM_K(k, xT_a, 128, k);

        if (t > 0) {
            #pragma unroll 2
            for (int k = 0; k < 64; k++) LSTM_K(k + 64, sHT_a, 132, k);
        }

        __syncthreads();

        float h0[8], h1[8];
        if (t > 0) {
            float4 p = *reinterpret_cast<const float4*>(&sHT[hx * 132 + r0]);
            float4 q = *reinterpret_cast<const float4*>(&sHT[hx * 132 + r0 + 4]);
            h0[0]=p.x; h0[1]=p.y; h0[2]=p.z; h0[3]=p.w;
            h0[4]=q.x; h0[5]=q.y; h0[6]=q.z; h0[7]=q.w;
            p = *reinterpret_cast<const float4*>(&sHT[(hx + 1) * 132 + r0]);
            q = *reinterpret_cast<const float4*>(&sHT[(hx + 1) * 132 + r0 + 4]);
            h1[0]=p.x; h1[1]=p.y; h1[2]=p.z; h1[3]=p.w;
            h1[4]=q.x; h1[5]=q.y; h1[6]=q.z; h1[7]=q.w;
        } else {
            #pragma unroll
            for (int i = 0; i < 8; i++) { h0[i] = 0.f; h1[i] = 0.f; }
        }

        float hn0[8], hn1[8];
        #pragma unroll
        for (int rp = 0; rp < 4; rp++) {
            float2 vi0 = unpack2(acc[0][0][rp]), vi1 = unpack2(acc[0][1][rp]);
            float2 vj0 = unpack2(acc[1][0][rp]), vj1 = unpack2(acc[1][1][rp]);
            float2 vf0 = unpack2(acc[2][0][rp]), vf1 = unpack2(acc[2][1][rp]);
            float2 vo0 = unpack2(acc[3][0][rp]), vo1 = unpack2(acc[3][1][rp]);
            #pragma unroll
            for (int h2 = 0; h2 < 2; h2++) {
                int i = rp * 2 + h2;
                int row = r0 + i;
                bool valid = (t < sAu[row]);
                float gi0 = (h2 ? vi0.y : vi0.x) + bg[0].x;
                float gi1 = (h2 ? vi1.y : vi1.x) + bg[0].y;
                float gj0 = (h2 ? vj0.y : vj0.x) + bg[1].x;
                float gj1 = (h2 ? vj1.y : vj1.x) + bg[1].y;
                float gf0 = (h2 ? vf0.y : vf0.x) + bg[2].x;
                float gf1 = (h2 ? vf1.y : vf1.x) + bg[2].y;
                float go0 = (h2 ? vo0.y : vo0.x) + bg[3].x;
                float go1 = (h2 ? vo1.y : vo1.x) + bg[3].y;

                float c0o = cc[i].x, c1o = cc[i].y;
                float cn0 = sig_f(gf0 + 1.f) * c0o + sig_f(gi0) * tanh_f(gj0);
                float cn1 = sig_f(gf1 + 1.f) * c1o + sig_f(gi1) * tanh_f(gj1);
                float hh0 = sig_f(go0) * tanh_f(cn0);
                float hh1 = sig_f(go1) * tanh_f(cn1);

                cc[i].x = valid ? cn0 : c0o;
                cc[i].y = valid ? cn1 : c1o;
                hn0[i] = valid ? hh0 : h0[i];
                hn1[i] = valid ? hh1 : h1[i];

                float2 yw = make_float2(valid ? hh0 : 0.f, valid ? hh1 : 0.f);
                *reinterpret_cast<float2*>(gy + ((size_t)sPb[row] * 5 + t) * 64 + hx) = yw;
            }
        }

        *reinterpret_cast<float4*>(&sHT[hx * 132 + r0])           = make_float4(hn0[0], hn0[1], hn0[2], hn0[3]);
        *reinterpret_cast<float4*>(&sHT[hx * 132 + r0 + 4])       = make_float4(hn0[4], hn0[5], hn0[6], hn0[7]);
        *reinterpret_cast<float4*>(&sHT[(hx + 1) * 132 + r0])     = make_float4(hn1[0], hn1[1], hn1[2], hn1[3]);
        *reinterpret_cast<float4*>(&sHT[(hx + 1) * 132 + r0 + 4]) = make_float4(hn1[4], hn1[5], hn1[6], hn1[7]);
    }
    asm volatile("cp.async.wait_group 0;" ::: "memory");
}

// ============================ Kernel 3: final =======================================
__global__ __launch_bounds__(256)
void final_kernel(const float* __restrict__ mask,
                  const float* __restrict__ ln3g, const float* __restrict__ ln3b,
                  const float* __restrict__ convw, const float* __restrict__ convb,
                  const int* __restrict__ au, float* __restrict__ out)
{
    int b = blockIdx.x * 8 + (threadIdx.x >> 5);
    int lane = threadIdx.x & 31;
    int a = au[b];

    float vals[20];
    float s = 0.f, q = 0.f;
    #pragma unroll
    for (int t = 0; t < 5; t++) {
        float v0 = 0.f, v1 = 0.f, v2 = 0.f, v3 = 0.f;
        if (t < a) {
            int rt = a - 1 - t;
            size_t fbase = ((size_t)b * 5 + t)  * 64;
            size_t bbase = ((size_t)b * 5 + rt) * 64;
            v0 = g_ys[0][fbase + lane];
            v1 = g_ys[0][fbase + lane + 32];
            v2 = g_ys[1][bbase + lane];
            v3 = g_ys[1][bbase + lane + 32];
        }
        vals[t * 4 + 0] = v0; vals[t * 4 + 1] = v1;
        vals[t * 4 + 2] = v2; vals[t * 4 + 3] = v3;
        s += v0 + v1 + v2 + v3;
        q += v0 * v0 + v1 * v1 + v2 * v2 + v3 * v3;
    }
    #pragma unroll
    for (int o = 16; o; o >>= 1) { s += __shfl_xor_sync(~0u, s, o); q += __shfl_xor_sync(~0u, q, o); }
    float m = s * (1.f / 640.f);
    float var = q * (1.f / 640.f) - m * m;
    float rs = rsqrtf(var + EPSf);

    float g0 = ln3g[lane],      c0 = ln3b[lane],      w0 = convw[lane];
    float g1 = ln3g[lane + 32], c1 = ln3b[lane + 32], w1 = convw[lane + 32];
    float g2 = ln3g[lane + 64], c2 = ln3b[lane + 64], w2 = convw[lane + 64];
    float g3 = ln3g[lane + 96], c3 = ln3b[lane + 96], w3 = convw[lane + 96];

    float accq = 0.f, msum = 0.f;
    #pragma unroll
    for (int t = 0; t < 5; t++) {
        float p =
            fmaxf((vals[t*4+0] - m) * rs * g0 + c0, 0.f) * w0 +
            fmaxf((vals[t*4+1] - m) * rs * g1 + c1, 0.f) * w1 +
            fmaxf((vals[t*4+2] - m) * rs * g2 + c2, 0.f) * w2 +
            fmaxf((vals[t*4+3] - m) * rs * g3 + c3, 0.f) * w3;
        float mk = mask[(size_t)b * 5 + t];
        accq += p * mk;
        msum += mk;
    }
    #pragma unroll
    for (int o = 16; o; o >>= 1) accq += __shfl_xor_sync(~0u, accq, o);
    if (lane == 0) out[b] = accq + convb[0] * msum;
}

// =====================================================================================
extern "C" void kernel_launch(void* const* d_in, const int* in_sizes, int n_in,
                              void* d_out, int out_size)
{
    (void)in_sizes; (void)n_in; (void)out_size;
    const float* ud     = (const float*)d_in[0];
    const float* action = (const float*)d_in[1];
    const float* mask   = (const float*)d_in[2];
    const float* ln0g   = (const float*)d_in[3];
    const float* ln0b   = (const float*)d_in[4];
    const float* W1     = (const float*)d_in[5];
    const float* b1     = (const float*)d_in[6];
    const float* ln1g   = (const float*)d_in[7];
    const float* ln1b   = (const float*)d_in[8];
    const float* W2     = (const float*)d_in[9];
    const float* b2     = (const float*)d_in[10];
    const float* ln2g   = (const float*)d_in[11];
    const float* ln2b   = (const float*)d_in[12];
    const float* fw_k   = (const float*)d_in[13];
    const float* fw_b   = (const float*)d_in[14];
    const float* bw_k   = (const float*)d_in[15];
    const float* bw_b   = (const float*)d_in[16];
    const float* ln3g   = (const float*)d_in[17];
    const float* ln3b   = (const float*)d_in[18];
    const float* convw  = (const float*)d_in[19];
    const float* convb  = (const float*)d_in[20];
    const int*   au     = (const int*)d_in[21];

    const int MLP_SMEM  = (128*64 + 64*132 + 64*100 + 640 + 64) * 4;   // 94976 B
    const int LSTM_SMEM = (32768 + 8192 + 8192 + 8448 + 256) * 4;      // 231424 B

    cudaFuncSetAttribute(mlp_kernel,             cudaFuncAttributeMaxDynamicSharedMemorySize, MLP_SMEM);
    cudaFuncSetAttribute(lstm_persistent_kernel, cudaFuncAttributeMaxDynamicSharedMemorySize, LSTM_SMEM);

    zero_cnt_kernel<<<1, 32>>>();
    hist_kernel<<<Bn / 512, 512>>>(au);
    prefix_kernel<<<1, 32>>>();
    scatter_kernel<<<Bn / 512, 512>>>(au);

    mlp_kernel<<<BT / 64, 128, MLP_SMEM>>>(ud, action, ln0g, ln0b, W1, b1,
                                           ln1g, ln1b, W2, b2, ln2g, ln2b);

    lstm_persistent_kernel<<<dim3(Bn / 128, 2), 512, LSTM_SMEM>>>(fw_k, fw_b, bw_k, bw_b, au);

    final_kernel<<<Bn / 8, 256>>>(mask, ln3g, ln3b, convw, convb, au, (float*)d_out);
}

// round 12
// speedup vs baseline: 1.1451x; 1.1451x over previous
#include <cuda_runtime.h>
#include <math.h>

#define Bn   65536
#define Tn   5
#define BT   (Bn*Tn)
#define EPSf 1e-12f

typedef unsigned long long u64;

__device__ float g_x[BT * 64];          // zero-init; invalid (t>=au) slots never written
__device__ float g_ys[2][BT * 64];
__device__ int   g_cnt[5];              // zero-init; prefix_kernel re-zeroes after use
__device__ int   g_cursor[5];
__device__ int   g_pbase[5];
__device__ int   g_vbase[6];
__device__ int   g_perm[Bn];

extern __shared__ float smem[];

__device__ __forceinline__ u64 splat2(float x) {
    u64 r; asm("mov.b64 %0, {%1, %1};" : "=l"(r) : "f"(x)); return r;
}
__device__ __forceinline__ void ffma2(u64& d, u64 a, u64 b) {
    asm("fma.rn.f32x2 %0, %1, %2, %0;" : "+l"(d) : "l"(a), "l"(b));
}
__device__ __forceinline__ void lds_v2u64(u64& a, u64& b, unsigned addr) {
    asm volatile("ld.shared.v2.u64 {%0, %1}, [%2];" : "=l"(a), "=l"(b) : "r"(addr));
}
__device__ __forceinline__ float2 unpack2(u64 v) {
    float2 f; asm("mov.b64 {%0, %1}, %2;" : "=f"(f.x), "=f"(f.y) : "l"(v)); return f;
}
__device__ __forceinline__ float sig_f(float x) { return __fdividef(1.f, 1.f + __expf(-x)); }
// MUFU.TANH: 1 MUFU op instead of EX2+RCP; abs err ~5e-4, well inside the 1e-3 gate
__device__ __forceinline__ float tanh_f(float x) {
    float y; asm("tanh.approx.f32 %0, %1;" : "=f"(y) : "f"(x)); return y;
}

#define CP16(dst, src) asm volatile("cp.async.ca.shared.global [%0], [%1], 16;" :: "r"(dst), "l"(src))
#define CP_COMMIT()    asm volatile("cp.async.commit_group;")

// ============================ au counting sort ======================================
__global__ __launch_bounds__(512)
void hist_kernel(const int* __restrict__ au) {
    __shared__ int h[5];
    int tid = threadIdx.x;
    if (tid < 5) h[tid] = 0;
    __syncthreads();
    atomicAdd(&h[5 - au[blockIdx.x * 512 + tid]], 1);
    __syncthreads();
    if (tid < 5) atomicAdd(&g_cnt[tid], h[tid]);
}
__global__ void prefix_kernel() {
    if (threadIdx.x == 0) {
        int s = 0, vs = 0;
        #pragma unroll
        for (int i = 0; i < 5; i++) {
            int c = g_cnt[i];
            g_cnt[i]    = 0;     // re-zero for the next graph replay
            g_cursor[i] = s;
            g_pbase[i]  = s;
            g_vbase[i]  = vs;
            s  += c;
            vs += c * (5 - i);
        }
        g_vbase[5] = vs;
    }
}
__global__ __launch_bounds__(512)
void scatter_kernel(const int* __restrict__ au) {
    int i = blockIdx.x * 512 + threadIdx.x;
    int lane = threadIdx.x & 31;
    int bkt = 5 - au[i];
    unsigned m = __match_any_sync(0xffffffffu, bkt);
    int leader = __ffs(m) - 1;
    int rank = __popc(m & ((1u << lane) - 1u));
    int base = 0;
    if (lane == leader) base = atomicAdd(&g_cursor[bkt], __popc(m));
    base = __shfl_sync(0xffffffffu, base, leader);
    g_perm[base + rank] = i;
}

// ============================ Kernel 1: fused MLP (R9/R10, proven) ==================
// 64 valid rows/CTA, 256 threads, 2 CTA/SM, thread tile 4x4.
__global__ __launch_bounds__(256)
void mlp_kernel(const float* __restrict__ ud, const float* __restrict__ act,
                const float* __restrict__ ln0g, const float* __restrict__ ln0b,
                const float* __restrict__ W1, const float* __restrict__ b1,
                const float* __restrict__ ln1g, const float* __restrict__ ln1b,
                const float* __restrict__ W2, const float* __restrict__ b2,
                const float* __restrict__ ln2g, const float* __restrict__ ln2b)
{
    const int vtot = g_vbase[5];
    if (blockIdx.x * 64 >= vtot) return;

    float* sW  = smem;
    float* sX  = sW + 128 * 64;
    float* sX2 = sX + 64 * 132;
    float* sP  = sX2 + 64 * 100;
    int*   sRowIdx = (int*)(sP + 640);

    const unsigned sW_a = (unsigned)__cvta_generic_to_shared(sW);
    const int tid = threadIdx.x;

    #pragma unroll
    for (int j = 0; j < 8; j++) {
        int f = tid + j * 256;
        reinterpret_cast<float4*>(sW)[f] = reinterpret_cast<const float4*>(W1)[f];
    }
    if (tid < 128) { sP[tid] = ln0g[tid]; sP[128 + tid] = ln0b[tid]; }
    if (tid < 64) {
        sP[256 + tid] = b1[tid];  sP[320 + tid] = ln1g[tid]; sP[384 + tid] = ln1b[tid];
        sP[448 + tid] = b2[tid];  sP[512 + tid] = ln2g[tid]; sP[576 + tid] = ln2b[tid];
    }

    if (tid < 64) {
        int v = blockIdx.x * 64 + tid;
        int row = -1;
        if (v < vtot) {
            int k = 0;
            #pragma unroll
            for (int j = 1; j < 5; j++) if (v >= g_vbase[j]) k = j;
            int L = 5 - k;
            int idx = v - g_vbase[k];
            int q = idx / L;
            int t = idx - q * L;
            int b = g_perm[g_pbase[k] + q];
            row = b * 5 + t;
        }
        sRowIdx[tid] = row;
    }
    __syncthreads();

    #pragma unroll
    for (int j = 0; j < 8; j++) {
        int f = tid + j * 256;
        int row = f >> 5, c4 = f & 31;
        int gr = sRowIdx[row];
        float4 v = make_float4(0.f, 0.f, 0.f, 0.f);
        if (gr >= 0) v = reinterpret_cast<const float4*>(ud + (size_t)gr * 128)[c4];
        *reinterpret_cast<float4*>(&sX[row * 132 + c4 * 4]) = v;
    }
    #pragma unroll
    for (int j = 0; j < 2; j++) {
        int f = tid + j * 256;
        int row = f >> 3, c4 = f & 7;
        int gr = sRowIdx[row];
        float4 v = make_float4(0.f, 0.f, 0.f, 0.f);
        if (gr >= 0) v = reinterpret_cast<const float4*>(act + (size_t)gr * 32)[c4];
        *reinterpret_cast<float4*>(&sX2[row * 100 + 64 + c4 * 4]) = v;
    }
    __syncthreads();

    const int w = tid >> 5, lane = tid & 31;

    for (int rr = 0; rr < 8; rr++) {
        int row = w * 8 + rr;
        float v0 = sX[row * 132 + lane];
        float v1 = sX[row * 132 + lane + 32];
        float v2 = sX[row * 132 + lane + 64];
        float v3 = sX[row * 132 + lane + 96];
        float s = v0 + v1 + v2 + v3;
        float q = v0 * v0 + v1 * v1 + v2 * v2 + v3 * v3;
        #pragma unroll
        for (int o = 16; o; o >>= 1) { s += __shfl_xor_sync(~0u, s, o); q += __shfl_xor_sync(~0u, q, o); }
        float m = s * (1.f / 128.f);
        float var = q * (1.f / 128.f) - m * m;
        float rs = rsqrtf(var + EPSf);
        sX[row * 132 + lane]      = (v0 - m) * rs * sP[lane]      + sP[128 + lane];
        sX[row * 132 + lane + 32] = (v1 - m) * rs * sP[lane + 32] + sP[128 + lane + 32];
        sX[row * 132 + lane + 64] = (v2 - m) * rs * sP[lane + 64] + sP[128 + lane + 64];
        sX[row * 132 + lane + 96] = (v3 - m) * rs * sP[lane + 96] + sP[128 + lane + 96];
    }
    __syncthreads();

    const int ty = tid >> 4, tx = tid & 15;
    const int ry = ty * 4, cx = tx * 4;

    u64 acc[4][2];
    #pragma unroll
    for (int i = 0; i < 4; i++) { acc[i][0] = 0ull; acc[i][1] = 0ull; }

    for (int k = 0; k < 128; k += 4) {
        float4 a4[4];
        #pragma unroll
        for (int i = 0; i < 4; i++)
            a4[i] = *reinterpret_cast<const float4*>(&sX[(ry + i) * 132 + k]);
        u64 w0[4], w1[4];
        #pragma unroll
        for (int kk = 0; kk < 4; kk++)
            lds_v2u64(w0[kk], w1[kk], sW_a + (unsigned)((k + kk) * 64 + cx) * 4u);
        #pragma unroll
        for (int kk = 0; kk < 4; kk++) {
            #pragma unroll
            for (int i = 0; i < 4; i++) {
                u64 s = splat2((&a4[i].x)[kk]);
                ffma2(acc[i][0], s, w0[kk]);
                ffma2(acc[i][1], s, w1[kk]);
            }
        }
    }
    __syncthreads();

    #pragma unroll
    for (int j = 0; j < 6; j++) {
        int f = tid + j * 256;
        reinterpret_cast<float4*>(sW)[f] = reinterpret_cast<const float4*>(W2)[f];
    }

    {
        #pragma unroll
        for (int i = 0; i < 4; i++) {
            float2 p0 = unpack2(acc[i][0]);
            float2 p1 = unpack2(acc[i][1]);
            float v0 = p0.x + sP[256 + cx], v1 = p0.y + sP[256 + cx + 1];
            float v2 = p1.x + sP[256 + cx + 2], v3 = p1.y + sP[256 + cx + 3];
            float s = v0 + v1 + v2 + v3;
            float q = v0 * v0 + v1 * v1 + v2 * v2 + v3 * v3;
            #pragma unroll
            for (int o = 1; o < 16; o <<= 1) { s += __shfl_xor_sync(~0u, s, o); q += __shfl_xor_sync(~0u, q, o); }
            float m = s * (1.f / 64.f);
            float var = q * (1.f / 64.f) - m * m;
            float rs = rsqrtf(var + EPSf);
            float4 o4;
            o4.x = fmaxf((v0 - m) * rs * sP[320 + cx + 0] + sP[384 + cx + 0], 0.f);
            o4.y = fmaxf((v1 - m) * rs * sP[320 + cx + 1] + sP[384 + cx + 1], 0.f);
            o4.z = fmaxf((v2 - m) * rs * sP[320 + cx + 2] + sP[384 + cx + 2], 0.f);
            o4.w = fmaxf((v3 - m) * rs * sP[320 + cx + 3] + sP[384 + cx + 3], 0.f);
            *reinterpret_cast<float4*>(&sX2[(ry + i) * 100 + cx]) = o4;
        }
    }
    __syncthreads();

    u64 acc2[4][2];
    #pragma unroll
    for (int i = 0; i < 4; i++) { acc2[i][0] = 0ull; acc2[i][1] = 0ull; }

    for (int k = 0; k < 96; k += 4) {
        float4 a4[4];
        #pragma unroll
        for (int i = 0; i < 4; i++)
            a4[i] = *reinterpret_cast<const float4*>(&sX2[(ry + i) * 100 + k]);
        u64 w0[4], w1[4];
        #pragma unroll
        for (int kk = 0; kk < 4; kk++)
            lds_v2u64(w0[kk], w1[kk], sW_a + (unsigned)((k + kk) * 64 + cx) * 4u);
        #pragma unroll
        for (int kk = 0; kk < 4; kk++) {
            #pragma unroll
            for (int i = 0; i < 4; i++) {
                u64 s = splat2((&a4[i].x)[kk]);
                ffma2(acc2[i][0], s, w0[kk]);
                ffma2(acc2[i][1], s, w1[kk]);
            }
        }
    }

    {
        #pragma unroll
        for (int i = 0; i < 4; i++) {
            float2 p0 = unpack2(acc2[i][0]);
            float2 p1 = unpack2(acc2[i][1]);
            float v0 = p0.x + sP[448 + cx], v1 = p0.y + sP[448 + cx + 1];
            float v2 = p1.x + sP[448 + cx + 2], v3 = p1.y + sP[448 + cx + 3];
            float s = v0 + v1 + v2 + v3;
            float q = v0 * v0 + v1 * v1 + v2 * v2 + v3 * v3;
            #pragma unroll
            for (int o = 1; o < 16; o <<= 1) { s += __shfl_xor_sync(~0u, s, o); q += __shfl_xor_sync(~0u, q, o); }
            float m = s * (1.f / 64.f);
            float var = q * (1.f / 64.f) - m * m;
            float rs = rsqrtf(var + EPSf);
            int gr = sRowIdx[ry + i];
            if (gr >= 0) {
                float4 o4;
                o4.x = fmaxf((v0 - m) * rs * sP[512 + cx + 0] + sP[576 + cx + 0], 0.f);
                o4.y = fmaxf((v1 - m) * rs * sP[512 + cx + 1] + sP[576 + cx + 1], 0.f);
                o4.z = fmaxf((v2 - m) * rs * sP[512 + cx + 2] + sP[576 + cx + 2], 0.f);
                o4.w = fmaxf((v3 - m) * rs * sP[512 + cx + 3] + sP[576 + cx + 3], 0.f);
                *reinterpret_cast<float4*>(&g_x[(size_t)gr * 64 + cx]) = o4;
            }
        }
    }
}

// ===================== Kernel 2: persistent LSTM (R10 structure) ====================
#define LSTM_K(wk, A_a, astr, ak) do {                                                   \
    float4 wij = *reinterpret_cast<const float4*>(sKp + (wk) * 256 + hp * 8);            \
    float4 wfo = *reinterpret_cast<const float4*>(sKp + (wk) * 256 + hp * 8 + 4);        \
    u64 a01, a23, a45, a67;                                                              \
    lds_v2u64(a01, a23, (A_a) + (unsigned)((ak) * (astr) + r0) * 4u);                    \
    lds_v2u64(a45, a67, (A_a) + (unsigned)((ak) * (astr) + r0 + 4) * 4u);                \
    u64 s_;                                                                              \
    s_ = splat2(wij.x); ffma2(acc[0][0][0],s_,a01); ffma2(acc[0][0][1],s_,a23);          \
                        ffma2(acc[0][0][2],s_,a45); ffma2(acc[0][0][3],s_,a67);          \
    s_ = splat2(wij.y); ffma2(acc[0][1][0],s_,a01); ffma2(acc[0][1][1],s_,a23);          \
                        ffma2(acc[0][1][2],s_,a45); ffma2(acc[0][1][3],s_,a67);          \
    s_ = splat2(wij.z); ffma2(acc[1][0][0],s_,a01); ffma2(acc[1][0][1],s_,a23);          \
                        ffma2(acc[1][0][2],s_,a45); ffma2(acc[1][0][3],s_,a67);          \
    s_ = splat2(wij.w); ffma2(acc[1][1][0],s_,a01); ffma2(acc[1][1][1],s_,a23);          \
                        ffma2(acc[1][1][2],s_,a45); ffma2(acc[1][1][3],s_,a67);          \
    s_ = splat2(wfo.x); ffma2(acc[2][0][0],s_,a01); ffma2(acc[2][0][1],s_,a23);          \
                        ffma2(acc[2][0][2],s_,a45); ffma2(acc[2][0][3],s_,a67);          \
    s_ = splat2(wfo.y); ffma2(acc[2][1][0],s_,a01); ffma2(acc[2][1][1],s_,a23);          \
                        ffma2(acc[2][1][2],s_,a45); ffma2(acc[2][1][3],s_,a67);          \
    s_ = splat2(wfo.z); ffma2(acc[3][0][0],s_,a01); ffma2(acc[3][0][1],s_,a23);          \
                        ffma2(acc[3][0][2],s_,a45); ffma2(acc[3][0][3],s_,a67);          \
    s_ = splat2(wfo.w); ffma2(acc[3][1][0],s_,a01); ffma2(acc[3][1][1],s_,a23);          \
                        ffma2(acc[3][1][2],s_,a45); ffma2(acc[3][1][3],s_,a67);          \
} while (0)

__global__ __launch_bounds__(512, 1)
void lstm_persistent_kernel(const float* __restrict__ fw_k, const float* __restrict__ fw_b,
                            const float* __restrict__ bw_k, const float* __restrict__ bw_b,
                            const int* __restrict__ au)
{
    float* sKp   = smem;
    float* stage = smem + 32768;
    float* xT    = smem + 40960;
    float* sHT   = smem + 49152;
    int*   sAu   = (int*)(smem + 57600);
    int*   sPb   = sAu + 128;

    const unsigned xT_a  = (unsigned)__cvta_generic_to_shared(xT);
    const unsigned sHT_a = (unsigned)__cvta_generic_to_shared(sHT);

    const int dir = blockIdx.y;
    const float* K    = dir ? bw_k : fw_k;
    const float* bias = dir ? bw_b : fw_b;
    float* gy = g_ys[dir];

    const int b0   = blockIdx.x * 128;
    const int tid  = threadIdx.x;
    const int lane = tid & 31, w = tid >> 5;
    const int hsub = lane & 7, rsub = lane >> 3;
    const int wcol = w & 3,  wrow = w >> 2;
    const int hp   = wcol * 8 + hsub;
    const int hx   = hp * 2;
    const int r0   = (wrow * 4 + rsub) * 8;

    const int mx = au[g_perm[b0]];

    {
        int row = tid >> 2, seg = tid & 3;
        int pb = g_perm[b0 + row];
        int a = au[pb];
        int ts = dir ? (a - 1) : 0;
        const float* src = g_x + ((size_t)pb * 5 + ts) * 64 + seg * 16;
        unsigned dst = (unsigned)__cvta_generic_to_shared(stage + row * 64 + seg * 16);
        #pragma unroll
        for (int q = 0; q < 4; q++) CP16(dst + q * 16, src + q * 4);
        CP_COMMIT();
        if (seg == 0) { sAu[row] = a; sPb[row] = pb; }
    }

    #pragma unroll
    for (int it = 0; it < 16; it++) {
        int f = tid + it * 512;
        int kk = f >> 6, c4 = f & 63;
        float4 v = reinterpret_cast<const float4*>(K + (size_t)kk * 256)[c4];
        int g   = c4 >> 4;
        int hp0 = (c4 & 15) * 2;
        *reinterpret_cast<float2*>(&sKp[kk * 256 + hp0 * 8 + g * 2])       = make_float2(v.x, v.y);
        *reinterpret_cast<float2*>(&sKp[kk * 256 + (hp0 + 1) * 8 + g * 2]) = make_float2(v.z, v.w);
    }

    float2 bg[4];
    #pragma unroll
    for (int g = 0; g < 4; g++)
        bg[g] = *reinterpret_cast<const float2*>(bias + g * 64 + hx);

    float2 cc[8];
    #pragma unroll
    for (int i = 0; i < 8; i++) cc[i] = make_float2(0.f, 0.f);

    for (int t = 0; t < mx; t++) {
        asm volatile("cp.async.wait_group 0;" ::: "memory");
        __syncthreads();

        {
            int row = tid >> 2, kc = (tid & 3) * 16;
            #pragma unroll
            for (int q = 0; q < 4; q++) {
                float4 v = *reinterpret_cast<const float4*>(&stage[row * 64 + kc + q * 4]);
                xT[(kc + q * 4 + 0) * 128 + row] = v.x;
                xT[(kc + q * 4 + 1) * 128 + row] = v.y;
                xT[(kc + q * 4 + 2) * 128 + row] = v.z;
                xT[(kc + q * 4 + 3) * 128 + row] = v.w;
            }
        }
        __syncthreads();

        if (t + 1 < mx) {
            int row = tid >> 2, seg = tid & 3;
            int pb = sPb[row];
            int a = sAu[row];
            int tt = t + 1;
            int ts = dir ? ((tt < a) ? (a - 1 - tt) : tt) : tt;
            const float* src = g_x + ((size_t)pb * 5 + ts) * 64 + seg * 16;
            unsigned dst = (unsigned)__cvta_generic_to_shared(stage + row * 64 + seg * 16);
            #pragma unroll
            for (int q = 0; q < 4; q++) CP16(dst + q * 16, src + q * 4);
            CP_COMMIT();
        } else {
            CP_COMMIT();
        }

        u64 acc[4][2][4];
        #pragma unroll
        for (int g = 0; g < 4; g++)
            #pragma unroll
            for (int e = 0; e < 2; e++)
                #pragma unroll
                for (int rp = 0; rp < 4; rp++) acc[g][e][rp] = 0ull;

        #pragma unroll 2
        for (int k = 0; k < 64; k++) LSTM_K(k, xT_a, 128, k);

        if (t > 0) {
            #pragma unroll 2
            for (int k = 0; k < 64; k++) LSTM_K(k + 64, sHT_a, 132, k);
        }

        __syncthreads();

        float h0[8], h1[8];
        if (t > 0) {
            float4 p = *reinterpret_cast<const float4*>(&sHT[hx * 132 + r0]);
            float4 q = *reinterpret_cast<const float4*>(&sHT[hx * 132 + r0 + 4]);
            h0[0]=p.x; h0[1]=p.y; h0[2]=p.z; h0[3]=p.w;
            h0[4]=q.x; h0[5]=q.y; h0[6]=q.z; h0[7]=q.w;
            p = *reinterpret_cast<const float4*>(&sHT[(hx + 1) * 132 + r0]);
            q = *reinterpret_cast<const float4*>(&sHT[(hx + 1) * 132 + r0 + 4]);
            h1[0]=p.x; h1[1]=p.y; h1[2]=p.z; h1[3]=p.w;
            h1[4]=q.x; h1[5]=q.y; h1[6]=q.z; h1[7]=q.w;
        } else {
            #pragma unroll
            for (int i = 0; i < 8; i++) { h0[i] = 0.f; h1[i] = 0.f; }
        }

        float hn0[8], hn1[8];
        #pragma unroll
        for (int rp = 0; rp < 4; rp++) {
            float2 vi0 = unpack2(acc[0][0][rp]), vi1 = unpack2(acc[0][1][rp]);
            float2 vj0 = unpack2(acc[1][0][rp]), vj1 = unpack2(acc[1][1][rp]);
            float2 vf0 = unpack2(acc[2][0][rp]), vf1 = unpack2(acc[2][1][rp]);
            float2 vo0 = unpack2(acc[3][0][rp]), vo1 = unpack2(acc[3][1][rp]);
            #pragma unroll
            for (int h2 = 0; h2 < 2; h2++) {
                int i = rp * 2 + h2;
                int row = r0 + i;
                bool valid = (t < sAu[row]);
                float gi0 = (h2 ? vi0.y : vi0.x) + bg[0].x;
                float gi1 = (h2 ? vi1.y : vi1.x) + bg[0].y;
                float gj0 = (h2 ? vj0.y : vj0.x) + bg[1].x;
                float gj1 = (h2 ? vj1.y : vj1.x) + bg[1].y;
                float gf0 = (h2 ? vf0.y : vf0.x) + bg[2].x;
                float gf1 = (h2 ? vf1.y : vf1.x) + bg[2].y;
                float go0 = (h2 ? vo0.y : vo0.x) + bg[3].x;
                float go1 = (h2 ? vo1.y : vo1.x) + bg[3].y;

                float c0o = cc[i].x, c1o = cc[i].y;
                float cn0 = sig_f(gf0 + 1.f) * c0o + sig_f(gi0) * tanh_f(gj0);
                float cn1 = sig_f(gf1 + 1.f) * c1o + sig_f(gi1) * tanh_f(gj1);
                float hh0 = sig_f(go0) * tanh_f(cn0);
                float hh1 = sig_f(go1) * tanh_f(cn1);

                cc[i].x = valid ? cn0 : c0o;
                cc[i].y = valid ? cn1 : c1o;
                hn0[i] = valid ? hh0 : h0[i];
                hn1[i] = valid ? hh1 : h1[i];

                float2 yw = make_float2(valid ? hh0 : 0.f, valid ? hh1 : 0.f);
                *reinterpret_cast<float2*>(gy + ((size_t)sPb[row] * 5 + t) * 64 + hx) = yw;
            }
        }

        *reinterpret_cast<float4*>(&sHT[hx * 132 + r0])           = make_float4(hn0[0], hn0[1], hn0[2], hn0[3]);
        *reinterpret_cast<float4*>(&sHT[hx * 132 + r0 + 4])       = make_float4(hn0[4], hn0[5], hn0[6], hn0[7]);
        *reinterpret_cast<float4*>(&sHT[(hx + 1) * 132 + r0])     = make_float4(hn1[0], hn1[1], hn1[2], hn1[3]);
        *reinterpret_cast<float4*>(&sHT[(hx + 1) * 132 + r0 + 4]) = make_float4(hn1[4], hn1[5], hn1[6], hn1[7]);
    }
    asm volatile("cp.async.wait_group 0;" ::: "memory");
}

// ============================ Kernel 3: final =======================================
__global__ __launch_bounds__(256)
void final_kernel(const float* __restrict__ mask,
                  const float* __restrict__ ln3g, const float* __restrict__ ln3b,
                  const float* __restrict__ convw, const float* __restrict__ convb,
                  const int* __restrict__ au, float* __restrict__ out)
{
    int b = blockIdx.x * 8 + (threadIdx.x >> 5);
    int lane = threadIdx.x & 31;
    int a = au[b];

    float vals[20];
    float s = 0.f, q = 0.f;
    #pragma unroll
    for (int t = 0; t < 5; t++) {
        float v0 = 0.f, v1 = 0.f, v2 = 0.f, v3 = 0.f;
        if (t < a) {
            int rt = a - 1 - t;
            size_t fbase = ((size_t)b * 5 + t)  * 64;
            size_t bbase = ((size_t)b * 5 + rt) * 64;
            v0 = g_ys[0][fbase + lane];
            v1 = g_ys[0][fbase + lane + 32];
            v2 = g_ys[1][bbase + lane];
            v3 = g_ys[1][bbase + lane + 32];
        }
        vals[t * 4 + 0] = v0; vals[t * 4 + 1] = v1;
        vals[t * 4 + 2] = v2; vals[t * 4 + 3] = v3;
        s += v0 + v1 + v2 + v3;
        q += v0 * v0 + v1 * v1 + v2 * v2 + v3 * v3;
    }
    #pragma unroll
    for (int o = 16; o; o >>= 1) { s += __shfl_xor_sync(~0u, s, o); q += __shfl_xor_sync(~0u, q, o); }
    float m = s * (1.f / 640.f);
    float var = q * (1.f / 640.f) - m * m;
    float rs = rsqrtf(var + EPSf);

    float g0 = ln3g[lane],      c0 = ln3b[lane],      w0 = convw[lane];
    float g1 = ln3g[lane + 32], c1 = ln3b[lane + 32], w1 = convw[lane + 32];
    float g2 = ln3g[lane + 64], c2 = ln3b[lane + 64], w2 = convw[lane + 64];
    float g3 = ln3g[lane + 96], c3 = ln3b[lane + 96], w3 = convw[lane + 96];

    float accq = 0.f, msum = 0.f;
    #pragma unroll
    for (int t = 0; t < 5; t++) {
        float p =
            fmaxf((vals[t*4+0] - m) * rs * g0 + c0, 0.f) * w0 +
            fmaxf((vals[t*4+1] - m) * rs * g1 + c1, 0.f) * w1 +
            fmaxf((vals[t*4+2] - m) * rs * g2 + c2, 0.f) * w2 +
            fmaxf((vals[t*4+3] - m) * rs * g3 + c3, 0.f) * w3;
        float mk = mask[(size_t)b * 5 + t];
        accq += p * mk;
        msum += mk;
    }
    #pragma unroll
    for (int o = 16; o; o >>= 1) accq += __shfl_xor_sync(~0u, accq, o);
    if (lane == 0) out[b] = accq + convb[0] * msum;
}

// =====================================================================================
extern "C" void kernel_launch(void* const* d_in, const int* in_sizes, int n_in,
                              void* d_out, int out_size)
{
    (void)in_sizes; (void)n_in; (void)out_size;
    const float* ud     = (const float*)d_in[0];
    const float* action = (const float*)d_in[1];
    const float* mask   = (const float*)d_in[2];
    const float* ln0g   = (const float*)d_in[3];
    const float* ln0b   = (const float*)d_in[4];
    const float* W1     = (const float*)d_in[5];
    const float* b1     = (const float*)d_in[6];
    const float* ln1g   = (const float*)d_in[7];
    const float* ln1b   = (const float*)d_in[8];
    const float* W2     = (const float*)d_in[9];
    const float* b2     = (const float*)d_in[10];
    const float* ln2g   = (const float*)d_in[11];
    const float* ln2b   = (const float*)d_in[12];
    const float* fw_k   = (const float*)d_in[13];
    const float* fw_b   = (const float*)d_in[14];
    const float* bw_k   = (const float*)d_in[15];
    const float* bw_b   = (const float*)d_in[16];
    const float* ln3g   = (const float*)d_in[17];
    const float* ln3b   = (const float*)d_in[18];
    const float* convw  = (const float*)d_in[19];
    const float* convb  = (const float*)d_in[20];
    const int*   au     = (const int*)d_in[21];

    const int MLP_SMEM  = (128*64 + 64*132 + 64*100 + 640 + 64) * 4;   // 94976 B
    const int LSTM_SMEM = (32768 + 8192 + 8192 + 8448 + 256) * 4;      // 231424 B

    cudaFuncSetAttribute(mlp_kernel,             cudaFuncAttributeMaxDynamicSharedMemorySize, MLP_SMEM);
    cudaFuncSetAttribute(lstm_persistent_kernel, cudaFuncAttributeMaxDynamicSharedMemorySize, LSTM_SMEM);

    hist_kernel<<<Bn / 512, 512>>>(au);
    prefix_kernel<<<1, 32>>>();
    scatter_kernel<<<Bn / 512, 512>>>(au);

    mlp_kernel<<<BT / 64, 256, MLP_SMEM>>>(ud, action, ln0g, ln0b, W1, b1,
                                           ln1g, ln1b, W2, b2, ln2g, ln2b);

    lstm_persistent_kernel<<<dim3(Bn / 128, 2), 512, LSTM_SMEM>>>(fw_k, fw_b, bw_k, bw_b, au);

    final_kernel<<<Bn / 8, 256>>>(mask, ln3g, ln3b, convw, convb, au, (float*)d_out);
}